// round 1
// baseline (speedup 1.0000x reference)
#include <cuda_runtime.h>
#include <cstdint>

// Problem constants
#define B_      16
#define C_      64
#define HW_     65536      // 256*256
#define W_      256

// Sort configuration: 4 LSD passes of 8 bits over the high 32 bits (ordered float).
// Low 22 bits of the 64-bit key hold (channel<<16 | spatial_index); keys are
// generated in spatial order, so stable LSD over the value bits alone yields
// the (value asc, spatial asc) order that matches jnp's stable argsort.
#define NBLK    16         // sort blocks per batch
#define BSIZE   4096       // elements per sort block
#define THREADS 256
#define IPT     16         // items per thread (BSIZE / THREADS)
#define NW      8          // warps per block

__device__ unsigned long long g_buf0[B_ * HW_];
__device__ unsigned long long g_buf1[B_ * HW_];
__device__ unsigned int       g_hist[B_ * 256 * NBLK];

__device__ __forceinline__ unsigned int f2ord(float f) {
    unsigned int u = __float_as_uint(f);
    return (u & 0x80000000u) ? ~u : (u | 0x80000000u);
}

// -------------------------------------------------------------------------
// Kernel 1: channel max + argmax (first occurrence), build 64-bit keys.
// Each thread handles 4 consecutive spatial positions via float4 loads.
// grid = 1024 blocks x 256 threads  (16 batches * 16384 float4 each)
// -------------------------------------------------------------------------
__global__ void compute_keys_kernel(const float* __restrict__ x) {
    int gid   = blockIdx.x * blockDim.x + threadIdx.x;   // 0 .. 262143
    int batch = gid >> 14;                               // 16384 float4 / batch
    int q     = gid & 16383;

    const float4* xb = reinterpret_cast<const float4*>(x)
                       + (size_t)batch * (C_ * (HW_ / 4)) + q;

    float4 best = xb[0];
    int c0 = 0, c1 = 0, c2 = 0, c3 = 0;
    #pragma unroll
    for (int c = 1; c < C_; ++c) {
        float4 v = xb[(size_t)c * (HW_ / 4)];
        if (v.x > best.x) { best.x = v.x; c0 = c; }
        if (v.y > best.y) { best.y = v.y; c1 = c; }
        if (v.z > best.z) { best.z = v.z; c2 = c; }
        if (v.w > best.w) { best.w = v.w; c3 = c; }
    }

    unsigned int s = (unsigned int)q * 4u;
    unsigned long long* out = g_buf0 + (size_t)batch * HW_ + s;
    out[0] = ((unsigned long long)f2ord(best.x) << 32) | ((unsigned)c0 << 16) | (s + 0u);
    out[1] = ((unsigned long long)f2ord(best.y) << 32) | ((unsigned)c1 << 16) | (s + 1u);
    out[2] = ((unsigned long long)f2ord(best.z) << 32) | ((unsigned)c2 << 16) | (s + 2u);
    out[3] = ((unsigned long long)f2ord(best.w) << 32) | ((unsigned)c3 << 16) | (s + 3u);
}

// -------------------------------------------------------------------------
// Kernel 2: per-block 256-bin histogram of one 8-bit digit.
// grid = 256 blocks (16 per batch), 256 threads.
// g_hist layout: [(batch*256 + bin)*NBLK + local_block]
// -------------------------------------------------------------------------
__global__ void hist_kernel(int which, int shift) {
    __shared__ unsigned int h[256];
    const unsigned long long* __restrict__ keys = which ? g_buf1 : g_buf0;
    int tid = threadIdx.x;
    h[tid] = 0;
    __syncthreads();

    int blk = blockIdx.x;
    size_t base = (size_t)blk * BSIZE;
    #pragma unroll
    for (int i = 0; i < IPT; ++i) {
        unsigned long long k = keys[base + i * THREADS + tid];
        atomicAdd(&h[(unsigned)(k >> shift) & 255u], 1u);
    }
    __syncthreads();

    int batch = blk >> 4, local = blk & 15;
    g_hist[((size_t)batch * 256 + tid) * NBLK + local] = h[tid];
}

// -------------------------------------------------------------------------
// Kernel 3: per-batch exclusive scan of the 4096 histogram entries
// (bin-major, block-minor). One block of 1024 threads per batch.
// -------------------------------------------------------------------------
__global__ void scan_kernel() {
    __shared__ unsigned int warp_sums[32];
    unsigned int* hist = g_hist + (size_t)blockIdx.x * 4096;
    int tid = threadIdx.x;
    int lane = tid & 31, w = tid >> 5;

    unsigned int v[4];
    unsigned int sum = 0;
    #pragma unroll
    for (int j = 0; j < 4; ++j) { v[j] = hist[tid * 4 + j]; sum += v[j]; }

    unsigned int inc = sum;
    #pragma unroll
    for (int o = 1; o < 32; o <<= 1) {
        unsigned int t = __shfl_up_sync(0xffffffffu, inc, o);
        if (lane >= o) inc += t;
    }
    if (lane == 31) warp_sums[w] = inc;
    __syncthreads();
    if (w == 0) {
        unsigned int ws = warp_sums[lane];
        #pragma unroll
        for (int o = 1; o < 32; o <<= 1) {
            unsigned int t = __shfl_up_sync(0xffffffffu, ws, o);
            if (lane >= o) ws += t;
        }
        warp_sums[lane] = ws;
    }
    __syncthreads();

    unsigned int excl = inc - sum + (w > 0 ? warp_sums[w - 1] : 0u);
    #pragma unroll
    for (int j = 0; j < 4; ++j) { hist[tid * 4 + j] = excl; excl += v[j]; }
}

// -------------------------------------------------------------------------
// Kernel 4: stable scatter. Warp-local stable ranks via __match_any_sync,
// cross-warp exclusive scan in smem, global offsets from g_hist (scanned).
// LAST pass decodes keys straight into d_out as float4.
// grid = 256 blocks, 256 threads.
// -------------------------------------------------------------------------
template <bool LAST>
__global__ void scatter_kernel(int which, int shift, float4* __restrict__ outv) {
    __shared__ unsigned int wh[NW][256];
    const unsigned long long* __restrict__ in  = which ? g_buf1 : g_buf0;
    unsigned long long*       __restrict__ out = which ? g_buf0 : g_buf1;

    int tid = threadIdx.x;
    for (int j = tid; j < NW * 256; j += THREADS)
        (&wh[0][0])[j] = 0;
    __syncthreads();

    int blk = blockIdx.x, batch = blk >> 4, local = blk & 15;
    int w = tid >> 5, lane = tid & 31;
    size_t base = (size_t)blk * BSIZE + (size_t)w * (32 * IPT);

    unsigned long long key[IPT];
    unsigned short rank[IPT];

    #pragma unroll
    for (int i = 0; i < IPT; ++i) {
        key[i] = in[base + i * 32 + lane];
        unsigned int d = (unsigned)(key[i] >> shift) & 255u;
        unsigned int mask = __match_any_sync(0xffffffffu, d);
        unsigned int prev = wh[w][d];
        unsigned int r = __popc(mask & ((1u << lane) - 1u));
        rank[i] = (unsigned short)(prev + r);
        __syncwarp();
        if (r == 0) wh[w][d] = prev + __popc(mask);
        __syncwarp();
    }
    __syncthreads();

    // Cross-warp exclusive scan per bin (one bin per thread).
    {
        unsigned int running = 0;
        #pragma unroll
        for (int q = 0; q < NW; ++q) {
            unsigned int t = wh[q][tid];
            wh[q][tid] = running;
            running += t;
        }
    }
    __syncthreads();

    #pragma unroll
    for (int i = 0; i < IPT; ++i) {
        unsigned int d = (unsigned)(key[i] >> shift) & 255u;
        unsigned int pos = g_hist[((size_t)batch * 256 + d) * NBLK + local]
                         + wh[w][d] + (unsigned int)rank[i];
        if (!LAST) {
            out[(size_t)batch * HW_ + pos] = key[i];
        } else {
            unsigned int hi = (unsigned int)(key[i] >> 32);
            unsigned int u  = (hi & 0x80000000u) ? (hi ^ 0x80000000u) : ~hi;
            unsigned int lo = (unsigned int)key[i];
            unsigned int s  = lo & 0xFFFFu;
            unsigned int c  = (lo >> 16) & 0xFFu;
            float4 o;
            o.x = __uint_as_float(u);
            o.y = (float)(c * (unsigned)HW_ + s);   // < 2^22, exact in f32
            o.z = (float)(s >> 8);                  // row (W=256)
            o.w = (float)(s & 255u);                // col
            outv[(size_t)batch * HW_ + pos] = o;
        }
    }
}

// -------------------------------------------------------------------------
extern "C" void kernel_launch(void* const* d_in, const int* in_sizes, int n_in,
                              void* d_out, int out_size) {
    const float* x = (const float*)d_in[0];
    float4* out = (float4*)d_out;

    compute_keys_kernel<<<1024, 256>>>(x);

    // Pass 1: bits [32,40)   buf0 -> buf1
    hist_kernel<<<256, 256>>>(0, 32);
    scan_kernel<<<16, 1024>>>();
    scatter_kernel<false><<<256, 256>>>(0, 32, nullptr);

    // Pass 2: bits [40,48)   buf1 -> buf0
    hist_kernel<<<256, 256>>>(1, 40);
    scan_kernel<<<16, 1024>>>();
    scatter_kernel<false><<<256, 256>>>(1, 40, nullptr);

    // Pass 3: bits [48,56)   buf0 -> buf1
    hist_kernel<<<256, 256>>>(0, 48);
    scan_kernel<<<16, 1024>>>();
    scatter_kernel<false><<<256, 256>>>(0, 48, nullptr);

    // Pass 4: bits [56,64)   buf1 -> d_out (decoded)
    hist_kernel<<<256, 256>>>(1, 56);
    scan_kernel<<<16, 1024>>>();
    scatter_kernel<true><<<256, 256>>>(1, 56, out);
}